// round 13
// baseline (speedup 1.0000x reference)
#include <cuda_runtime.h>
#include <cstdint>
#include <cstddef>
#include <math.h>

#define B_TOTAL 512
#define T_LEN   256
#define HID     128
#define G4      512
#define WINDOW  8
#define ENCO    128
#define R_ROWS  4
#define NCTA    128
#define NTHR    512
#define K4_SM   24           // k-quads in smem: k 0..95
#define TAIL_P  16           // k-pairs 48..63 (k 96..127) in regs, ONE gate col
#define BT      (B_TOTAL * T_LEN)

typedef unsigned long long ull;

__device__ __forceinline__ ull ffma2(ull a, ull b, ull c) {
    ull d;
    asm("fma.rn.f32x2 %0, %1, %2, %3;" : "=l"(d) : "l"(a), "l"(b), "l"(c));
    return d;
}
__device__ __forceinline__ float lo32(ull v) { return __uint_as_float((unsigned)v); }
__device__ __forceinline__ float hi32(ull v) { return __uint_as_float((unsigned)(v >> 32)); }
__device__ __forceinline__ ull pack2(float a, float b) {
    return (ull)__float_as_uint(a) | ((ull)__float_as_uint(b) << 32);
}
__device__ __forceinline__ float sigf(float x) {
    return __fdividef(1.f, 1.f + __expf(-x));
}
__device__ __forceinline__ float tanhf_(float x) {
    return 1.f - __fdividef(2.f, 1.f + __expf(2.f * x));
}

struct Smem {
    ull   Wq[K4_SM][G4][2];       // 196608 B : W_hh k 0..95
    alignas(16) ull h2[2][R_ROWS][HID/2];  // 4096 B : double-buffered h
    float part[R_ROWS][HID][4];   //   8192 B : tail partials [row][u][gate] (init staging too)
    float wihs[5][G4];            //  10240 B : W_ih transposed [j][col]
    float tout[R_ROWS][T_LEN];    //   4096 B
    float intv[R_ROWS][T_LEN];    //   4096 B
    float xv[R_ROWS][WINDOW][5];  //    640 B
    float red2[16];               //     64 B
    float Esm[R_ROWS];            //     16 B
};                                // 228048 B

// fc1 weights as transposed pairs
__device__ ull g_fc1p[64 * HID];

__global__ void prep_fc1(const float* __restrict__ fc1_w) {
    int idx = blockIdx.x * blockDim.x + threadIdx.x;
    if (idx < 64 * HID) {
        int k2 = idx >> 7, u = idx & 127;
        g_fc1p[idx] = pack2(fc1_w[u * HID + 2 * k2], fc1_w[u * HID + 2 * k2 + 1]);
    }
}

__global__ __launch_bounds__(NTHR, 1)
void modnn_kernel(const float* __restrict__ X,
                  const float* __restrict__ W_ih, const float* __restrict__ W_hh,
                  const float* __restrict__ b_ih, const float* __restrict__ b_hh,
                  const float* __restrict__ fc1_b,
                  const float* __restrict__ fc2_w, const float* __restrict__ fc2_b,
                  const float* __restrict__ int1_w, const float* __restrict__ int1_b,
                  const float* __restrict__ int3_w, const float* __restrict__ int3_b,
                  const float* __restrict__ scale_w, const float* __restrict__ zone_w,
                  float* __restrict__ out)
{
    extern __shared__ char smem_raw[];
    Smem* s = reinterpret_cast<Smem*>(smem_raw);
    const int tid  = threadIdx.x;
    const int b0   = blockIdx.x * R_ROWS;
    const int warp = tid >> 5;
    const int lane = tid & 31;
    const int u    = warp * 8 + (lane >> 2);   // unit 0..127
    const int r    = lane & 3;                 // my row 0..3

    // ---- stage W_hh k=0..95 as [k4][col] 16B quads ----
    for (int idx = tid; idx < K4_SM * G4; idx += NTHR) {
        int k4 = idx >> 9, col = idx & 511;
        const float* wr = W_hh + (size_t)col * HID + 4 * k4;
        s->Wq[k4][col][0] = pack2(wr[0], wr[1]);
        s->Wq[k4][col][1] = pack2(wr[2], wr[3]);
    }
    // x-part weights transposed
    for (int idx = tid; idx < 5 * G4; idx += NTHR) {
        int j = idx >> 9, col = idx & 511;
        s->wihs[j][col] = W_ih[col * 5 + j];
    }
    // int-module staging into part buffer (2048 floats available, need 640)
    {
        float* stg = &s->part[0][0][0];
        for (int idx = tid; idx < HID * 3; idx += NTHR) stg[idx] = int1_w[idx];
        for (int idx = tid; idx < HID; idx += NTHR) {
            stg[384 + idx] = int1_b[idx];
            stg[512 + idx] = int3_w[idx];
        }
    }

    // ---- per-thread invariants ----
    float btr[4];
    #pragma unroll
    for (int g = 0; g < 4; ++g) {
        int col = u + g * 128;
        btr[g] = b_ih[col] + b_hh[col];
    }
    // W_hh tail (k 96..127) for MY GATE column (col = u + r*128)
    ull wt[TAIL_P];
    {
        const ull* p = reinterpret_cast<const ull*>(W_hh + (size_t)(u + r * 128) * HID + 96);
        #pragma unroll
        for (int j = 0; j < TAIL_P; ++j) wt[j] = p[j];
    }
    // ext-head mapping: warp -> row (warp>>2), unit = (warp&3)*32 + lane
    const int rE = warp >> 2;
    const int uE = (warp & 3) * 32 + lane;
    const float b1r  = fc1_b[uE];
    const float w2r  = fc2_w[uE];
    const float zone = zone_w[0];
    const float fcb2 = fc2_b[0];
    const float i3b  = int3_b[0];
    const float scl  = scale_w[0];
    __syncthreads();

    // ---- precompute int_all; emit constant outputs; init tout/h/Esm ----
    {
        const float* stg = &s->part[0][0][0];
        for (int it = tid; it < R_ROWS * T_LEN; it += NTHR) {
            int rr = it >> 8, tt = it & 255;
            const float* Xb = X + (size_t)(b0 + rr) * (T_LEN * 7) + tt * 7;
            float x0 = Xb[3], x1 = Xb[4], x2 = Xb[5];
            float acc = 0.f;
            #pragma unroll 8
            for (int uu = 0; uu < HID; ++uu) {
                float v = fmaf(stg[uu*3], x0, fmaf(stg[uu*3+1], x1, fmaf(stg[uu*3+2], x2, stg[384+uu])));
                v = fmaxf(v, 0.f);
                acc = fmaf(v, stg[512 + uu], acc);
            }
            float val = scl * (1.f / (1.f + expf(-(acc + i3b))));
            s->intv[rr][tt] = val;
            size_t base = (size_t)(b0 + rr) * T_LEN + tt;
            out[(size_t)BT + base]   = Xb[6];                          // HVAC_list
            out[3*(size_t)BT + base] = (tt >= WINDOW) ? val : 0.f;     // Int_list
            if (tt < WINDOW) {
                out[base]                = Xb[0];                      // TOut[:, :w]
                out[2*(size_t)BT + base] = 0.f;                        // Ext zeros
                s->tout[rr][tt] = Xb[0];
            }
        }
        if (tid < R_ROWS)
            s->Esm[tid] = X[(size_t)(b0 + tid) * (T_LEN * 7) + WINDOW * 7];
    }
    __syncthreads();   // staging done before h-buffer 0 init (part overlaps nothing)
    // init h buffer 0
    for (int idx = tid; idx < R_ROWS * (HID/2); idx += NTHR)
        s->h2[0][idx >> 6][idx & 63] = pack2(1.f, 1.f);
    float cst = 1.f;   // cell state for (r, u)
    __syncthreads();

    // ================= main sequential time loop =================
    for (int i = WINDOW; i < T_LEN; ++i) {
        const bool  enc   = (i < ENCO);
        const float ratio = enc ? (float)i * (1.f / ENCO) : 0.f;

        // ---- window build (32 threads) ----
        if (tid < R_ROWS * WINDOW) {
            int rr = tid >> 3, tt = tid & 7;
            int pos = i - (WINDOW - 1) + tt;
            const float* Xb = X + (size_t)(b0 + rr) * (T_LEN * 7);
            float TO;
            if (tt == WINDOW - 1) {
                TO = s->Esm[rr];
                s->tout[rr][i] = TO;
                out[(size_t)(b0 + rr) * T_LEN + i] = TO;
            } else {
                TO = s->tout[rr][pos];
            }
            float e0 = enc ? fmaf(Xb[pos * 7], ratio, TO * (1.f - ratio)) : TO;
            s->xv[rr][tt][0] = e0;
            #pragma unroll
            for (int j = 1; j < 5; ++j) s->xv[rr][tt][j] = Xb[pos * 7 + j];
        }
        __syncthreads();

        // ---- 8 LSTM sub-steps, ONE CTA barrier each ----
        #pragma unroll 1
        for (int st = 0; st < WINDOW; ++st) {
            const int pb = st & 1;
            const ulonglong2* hq0 = reinterpret_cast<const ulonglong2*>(s->h2[pb][0]);
            const ulonglong2* hq1 = reinterpret_cast<const ulonglong2*>(s->h2[pb][1]);
            const ulonglong2* hq2 = reinterpret_cast<const ulonglong2*>(s->h2[pb][2]);
            const ulonglong2* hq3 = reinterpret_cast<const ulonglong2*>(s->h2[pb][3]);

            // ---- tail: my gate col (u + r*128), k 96..127, ALL 4 rows ----
            ull t0 = 0, t1 = 0, t2 = 0, t3 = 0;
            #pragma unroll
            for (int q = 0; q < TAIL_P / 2; ++q) {
                ull wa = wt[2*q], wb = wt[2*q+1];
                ulonglong2 h0 = hq0[K4_SM + q], h1 = hq1[K4_SM + q];
                ulonglong2 h2 = hq2[K4_SM + q], h3 = hq3[K4_SM + q];
                t0 = ffma2(wa, h0.x, t0);  t0 = ffma2(wb, h0.y, t0);
                t1 = ffma2(wa, h1.x, t1);  t1 = ffma2(wb, h1.y, t1);
                t2 = ffma2(wa, h2.x, t2);  t2 = ffma2(wb, h2.y, t2);
                t3 = ffma2(wa, h3.x, t3);  t3 = ffma2(wb, h3.y, t3);
            }
            s->part[0][u][r] = lo32(t0) + hi32(t0);
            s->part[1][u][r] = lo32(t1) + hi32(t1);
            s->part[2][u][r] = lo32(t2) + hi32(t2);
            s->part[3][u][r] = lo32(t3) + hi32(t3);

            // ---- main dots: my 4 gate cols x my row, k 0..95 ----
            ull a0 = 0, a1 = 0, a2 = 0, a3 = 0;
            const ulonglong2* hr = (r == 0) ? hq0 : (r == 1) ? hq1 : (r == 2) ? hq2 : hq3;
            #pragma unroll 2
            for (int k4 = 0; k4 < K4_SM; ++k4) {
                ulonglong2 hh = hr[k4];
                ulonglong2 q0 = *reinterpret_cast<const ulonglong2*>(&s->Wq[k4][u][0]);
                ulonglong2 q1 = *reinterpret_cast<const ulonglong2*>(&s->Wq[k4][u + 128][0]);
                ulonglong2 q2 = *reinterpret_cast<const ulonglong2*>(&s->Wq[k4][u + 256][0]);
                ulonglong2 q3 = *reinterpret_cast<const ulonglong2*>(&s->Wq[k4][u + 384][0]);
                a0 = ffma2(q0.x, hh.x, a0);  a0 = ffma2(q0.y, hh.y, a0);
                a1 = ffma2(q1.x, hh.x, a1);  a1 = ffma2(q1.y, hh.y, a1);
                a2 = ffma2(q2.x, hh.x, a2);  a2 = ffma2(q2.y, hh.y, a2);
                a3 = ffma2(q3.x, hh.x, a3);  a3 = ffma2(q3.y, hh.y, a3);
            }
            __syncwarp();   // part exchange ready (writers are my quad-mates)

            // ---- x-part from smem ----
            float f0 = btr[0], f1 = btr[1], f2 = btr[2], f3 = btr[3];
            #pragma unroll
            for (int j = 0; j < 5; ++j) {
                float xj = s->xv[r][st][j];
                f0 = fmaf(xj, s->wihs[j][u],       f0);
                f1 = fmaf(xj, s->wihs[j][u + 128], f1);
                f2 = fmaf(xj, s->wihs[j][u + 256], f2);
                f3 = fmaf(xj, s->wihs[j][u + 384], f3);
            }

            float4 pr = *reinterpret_cast<const float4*>(&s->part[r][u][0]);
            float gi = f0 + lo32(a0) + hi32(a0) + pr.x;
            float gf = f1 + lo32(a1) + hi32(a1) + pr.y;
            float gg = f2 + lo32(a2) + hi32(a2) + pr.z;
            float go = f3 + lo32(a3) + hi32(a3) + pr.w;

            // ---- phase 2 (thread-local) ----
            cst = sigf(gf) * cst + sigf(gi) * tanhf_(gg);
            float hv = sigf(go) * tanhf_(cst);
            reinterpret_cast<float*>(&s->h2[0][0][0])[((pb ^ 1) * R_ROWS + r) * HID + u] = hv;
            __syncthreads();
        }

        // ---- ext head: warp -> row rE, unit uE (final h in buffer 0) ----
        {
            const ull* hA = s->h2[0][rE];
            ull A = 0;
            #pragma unroll 8
            for (int k2 = 0; k2 < 64; ++k2)
                A = ffma2(__ldg(&g_fc1p[k2 * HID + uE]), hA[k2], A);
            float p = fmaxf(lo32(A) + hi32(A) + b1r, 0.f) * w2r;
            #pragma unroll
            for (int m = 16; m > 0; m >>= 1)
                p += __shfl_xor_sync(0xFFFFFFFFu, p, m);
            if (lane == 0) s->red2[warp] = p;
        }
        __syncthreads();

        // ---- scalar tail: ext, total, E update (one thread per row) ----
        if (tid < R_ROWS) {
            int rr = tid;
            float dot = s->red2[rr*4] + s->red2[rr*4+1] + s->red2[rr*4+2] + s->red2[rr*4+3];
            float ext = dot + fcb2;
            const float* Xb = X + (size_t)(b0 + rr) * (T_LEN * 7);
            float hv = Xb[i * 7 + 6];
            float it = s->intv[rr][i];
            float total = ext + hv + it;
            out[2*(size_t)BT + (size_t)(b0 + rr) * T_LEN + i] = ext;
            float E = s->Esm[rr];
            if (enc) E = ratio * Xb[i * 7] + (1.f - ratio) * E + total * zone;
            else     E = total * zone + E;
            s->Esm[rr] = E;
        }
        __syncthreads();
    }
}

extern "C" void kernel_launch(void* const* d_in, const int* in_sizes, int n_in,
                              void* d_out, int out_size) {
    const float* X       = (const float*)d_in[0];
    const float* W_ih    = (const float*)d_in[1];
    const float* W_hh    = (const float*)d_in[2];
    const float* b_ih    = (const float*)d_in[3];
    const float* b_hh    = (const float*)d_in[4];
    const float* fc1_w   = (const float*)d_in[5];
    const float* fc1_b   = (const float*)d_in[6];
    const float* fc2_w   = (const float*)d_in[7];
    const float* fc2_b   = (const float*)d_in[8];
    const float* int1_w  = (const float*)d_in[9];
    const float* int1_b  = (const float*)d_in[10];
    const float* int3_w  = (const float*)d_in[11];
    const float* int3_b  = (const float*)d_in[12];
    const float* scale_w = (const float*)d_in[13];
    const float* zone_w  = (const float*)d_in[14];
    float* out = (float*)d_out;

    prep_fc1<<<64, 128>>>(fc1_w);

    size_t smem = sizeof(Smem);
    cudaFuncSetAttribute(modnn_kernel, cudaFuncAttributeMaxDynamicSharedMemorySize, (int)smem);
    modnn_kernel<<<NCTA, NTHR, smem>>>(X, W_ih, W_hh, b_ih, b_hh,
                                       fc1_b, fc2_w, fc2_b,
                                       int1_w, int1_b, int3_w, int3_b,
                                       scale_w, zone_w, out);
}

// round 14
// speedup vs baseline: 1.0396x; 1.0396x over previous
#include <cuda_runtime.h>
#include <cstdint>
#include <cstddef>
#include <math.h>

#define B_TOTAL 512
#define T_LEN   256
#define HID     128
#define G4      512
#define WINDOW  8
#define ENCO    128
#define R_ROWS  4
#define NCTA    128
#define NTHR    512
#define K4_SM   24           // k-quads in smem: k 0..95 (group0: 0..11, group1: 12..23)
#define BT      (B_TOTAL * T_LEN)

typedef unsigned long long ull;

__device__ __forceinline__ ull ffma2(ull a, ull b, ull c) {
    ull d;
    asm("fma.rn.f32x2 %0, %1, %2, %3;" : "=l"(d) : "l"(a), "l"(b), "l"(c));
    return d;
}
__device__ __forceinline__ float lo32(ull v) { return __uint_as_float((unsigned)v); }
__device__ __forceinline__ float hi32(ull v) { return __uint_as_float((unsigned)(v >> 32)); }
__device__ __forceinline__ ull pack2(float a, float b) {
    return (ull)__float_as_uint(a) | ((ull)__float_as_uint(b) << 32);
}
__device__ __forceinline__ float sigf(float x) {
    return __fdividef(1.f, 1.f + __expf(-x));
}
__device__ __forceinline__ float tanhf_(float x) {
    return 1.f - __fdividef(2.f, 1.f + __expf(2.f * x));
}

struct Smem {
    ull   Wq[K4_SM][G4][2];        // 196608 B : W_hh k 0..95
    alignas(16) ull h2[R_ROWS][HID/2];   // 2048 B : hidden state (single buffer)
    float gp[2][R_ROWS][G4];       //  16384 B : gate partials per K-half
    float tout[R_ROWS][T_LEN];     //   4096 B
    float intv[R_ROWS][T_LEN];     //   4096 B
    float xv[R_ROWS][WINDOW][5];   //    640 B
    float red[R_ROWS][4];          //     64 B
    float Esm[R_ROWS];             //     16 B
    float stage[640];              //   2560 B (init only)
};                                 // ~226.5 KB

// fc1 weights as transposed pairs
__device__ ull g_fc1p[64 * HID];
// W_hh tail (k 96..127) packed as pairs: g_whhT[col*16 + q] = pack(W[col][96+2q], W[col][97+2q])
__device__ ull g_whhT[G4 * 16];

__global__ void prep_weights(const float* __restrict__ fc1_w,
                             const float* __restrict__ W_hh) {
    int idx = blockIdx.x * blockDim.x + threadIdx.x;   // 0..8191
    if (idx < 64 * HID) {
        int k2 = idx >> 7, u = idx & 127;
        g_fc1p[idx] = pack2(fc1_w[u * HID + 2 * k2], fc1_w[u * HID + 2 * k2 + 1]);
    }
    if (idx < G4 * 16) {
        int col = idx >> 4, q = idx & 15;
        g_whhT[idx] = pack2(W_hh[col * HID + 96 + 2 * q], W_hh[col * HID + 97 + 2 * q]);
    }
}

// K-half dot: smem quads [KQ0, KQ0+12); tail weights prefetched from L2 (g_whhT).
// All loop indices compile-time -> every smem address is base + immediate.
template<int KQ0>
__device__ __forceinline__ void dot_half(const Smem* __restrict__ s, int c2,
                                         const ulonglong2* __restrict__ tA,
                                         const ulonglong2* __restrict__ tB,
                                         ull (&a)[8])
{
    // prefetch tail weights (L2-resident; MLP=8 hides latency under main loop)
    ulonglong2 twA[4], twB[4];
    #pragma unroll
    for (int j = 0; j < 4; ++j) { twA[j] = __ldg(tA + j); twB[j] = __ldg(tB + j); }

    const ulonglong2* hq0 = reinterpret_cast<const ulonglong2*>(s->h2[0]);
    const ulonglong2* hq1 = reinterpret_cast<const ulonglong2*>(s->h2[1]);
    const ulonglong2* hq2 = reinterpret_cast<const ulonglong2*>(s->h2[2]);
    const ulonglong2* hq3 = reinterpret_cast<const ulonglong2*>(s->h2[3]);
    #pragma unroll
    for (int j = 0; j < 12; ++j) {
        const int k4 = KQ0 + j;
        ulonglong2 w0 = *reinterpret_cast<const ulonglong2*>(&s->Wq[k4][c2][0]);
        ulonglong2 w1 = *reinterpret_cast<const ulonglong2*>(&s->Wq[k4][c2 + 256][0]);
        ulonglong2 h0 = hq0[k4], h1 = hq1[k4], h2 = hq2[k4], h3 = hq3[k4];
        a[0] = ffma2(w0.x, h0.x, a[0]);  a[0] = ffma2(w0.y, h0.y, a[0]);
        a[4] = ffma2(w1.x, h0.x, a[4]);  a[4] = ffma2(w1.y, h0.y, a[4]);
        a[1] = ffma2(w0.x, h1.x, a[1]);  a[1] = ffma2(w0.y, h1.y, a[1]);
        a[5] = ffma2(w1.x, h1.x, a[5]);  a[5] = ffma2(w1.y, h1.y, a[5]);
        a[2] = ffma2(w0.x, h2.x, a[2]);  a[2] = ffma2(w0.y, h2.y, a[2]);
        a[6] = ffma2(w1.x, h2.x, a[6]);  a[6] = ffma2(w1.y, h2.y, a[6]);
        a[3] = ffma2(w0.x, h3.x, a[3]);  a[3] = ffma2(w0.y, h3.y, a[3]);
        a[7] = ffma2(w1.x, h3.x, a[7]);  a[7] = ffma2(w1.y, h3.y, a[7]);
    }
    // tail: k-pairs [48+8kh, 56+8kh) -> h ull-pair base 24 (kh=0) or 28 (kh=1)
    #pragma unroll
    for (int j = 0; j < 4; ++j) {
        const int hb = (KQ0 == 0 ? 24 : 28) + j;
        ulonglong2 h0 = hq0[hb], h1 = hq1[hb], h2 = hq2[hb], h3 = hq3[hb];
        ull wa0 = twA[j].x, wb0 = twA[j].y;
        ull wa1 = twB[j].x, wb1 = twB[j].y;
        a[0] = ffma2(wa0, h0.x, a[0]);  a[0] = ffma2(wb0, h0.y, a[0]);
        a[4] = ffma2(wa1, h0.x, a[4]);  a[4] = ffma2(wb1, h0.y, a[4]);
        a[1] = ffma2(wa0, h1.x, a[1]);  a[1] = ffma2(wb0, h1.y, a[1]);
        a[5] = ffma2(wa1, h1.x, a[5]);  a[5] = ffma2(wb1, h1.y, a[5]);
        a[2] = ffma2(wa0, h2.x, a[2]);  a[2] = ffma2(wb0, h2.y, a[2]);
        a[6] = ffma2(wa1, h2.x, a[6]);  a[6] = ffma2(wb1, h2.y, a[6]);
        a[3] = ffma2(wa0, h3.x, a[3]);  a[3] = ffma2(wb0, h3.y, a[3]);
        a[7] = ffma2(wa1, h3.x, a[7]);  a[7] = ffma2(wb1, h3.y, a[7]);
    }
}

__global__ __launch_bounds__(NTHR, 1)
void modnn_kernel(const float* __restrict__ X,
                  const float* __restrict__ W_ih, const float* __restrict__ W_hh,
                  const float* __restrict__ b_ih, const float* __restrict__ b_hh,
                  const float* __restrict__ fc1_b,
                  const float* __restrict__ fc2_w, const float* __restrict__ fc2_b,
                  const float* __restrict__ int1_w, const float* __restrict__ int1_b,
                  const float* __restrict__ int3_w, const float* __restrict__ int3_b,
                  const float* __restrict__ scale_w, const float* __restrict__ zone_w,
                  float* __restrict__ out)
{
    extern __shared__ char smem_raw[];
    Smem* s = reinterpret_cast<Smem*>(smem_raw);
    const int tid = threadIdx.x;
    const int b0  = blockIdx.x * R_ROWS;
    const int kh  = tid >> 8;        // K-half group: 0 or 1 (warp-uniform)
    const int c2  = tid & 255;       // my column base (cols c2 and c2+256)

    // tail-weight pointers (L2-resident)
    const ulonglong2* tA = reinterpret_cast<const ulonglong2*>(g_whhT + (size_t)c2 * 16 + kh * 8);
    const ulonglong2* tB = reinterpret_cast<const ulonglong2*>(g_whhT + (size_t)(c2 + 256) * 16 + kh * 8);

    // ---- stage W_hh k=0..95 as [k4][col] 16B quads ----
    for (int idx = tid; idx < K4_SM * G4; idx += NTHR) {
        int k4 = idx >> 9, col = idx & 511;
        const float* wr = W_hh + (size_t)col * HID + 4 * k4;
        s->Wq[k4][col][0] = pack2(wr[0], wr[1]);
        s->Wq[k4][col][1] = pack2(wr[2], wr[3]);
    }
    // int-module staging
    for (int idx = tid; idx < HID * 3; idx += NTHR) s->stage[idx] = int1_w[idx];
    for (int idx = tid; idx < HID; idx += NTHR) {
        s->stage[384 + idx] = int1_b[idx];
        s->stage[512 + idx] = int3_w[idx];
    }

    // ---- per-thread invariants (x-part weights only for kh==0 group) ----
    float wihA[5], wihB[5];
    float btA = 0.f, btB = 0.f;
    if (kh == 0) {
        #pragma unroll
        for (int j = 0; j < 5; ++j) {
            wihA[j] = W_ih[c2 * 5 + j];
            wihB[j] = W_ih[(c2 + 256) * 5 + j];
        }
        btA = b_ih[c2] + b_hh[c2];
        btB = b_ih[c2 + 256] + b_hh[c2 + 256];
    }

    // phase-2 mapping: thread <-> (row r2, unit u2)
    const int r2 = tid >> 7;
    const int u2 = tid & 127;
    const float b1r  = fc1_b[u2];
    const float w2r  = fc2_w[u2];
    const float zone = zone_w[0];
    const float fcb2 = fc2_b[0];
    const float i3b  = int3_b[0];
    const float scl  = scale_w[0];
    __syncthreads();

    // ---- precompute int_all; emit constant outputs; init tout/h/Esm ----
    {
        const float* tmp = s->stage;
        for (int it = tid; it < R_ROWS * T_LEN; it += NTHR) {
            int rr = it >> 8, tt = it & 255;
            const float* Xb = X + (size_t)(b0 + rr) * (T_LEN * 7) + tt * 7;
            float x0 = Xb[3], x1 = Xb[4], x2 = Xb[5];
            float acc = 0.f;
            #pragma unroll 8
            for (int uu = 0; uu < HID; ++uu) {
                float v = fmaf(tmp[uu*3], x0, fmaf(tmp[uu*3+1], x1, fmaf(tmp[uu*3+2], x2, tmp[384+uu])));
                v = fmaxf(v, 0.f);
                acc = fmaf(v, tmp[512 + uu], acc);
            }
            float val = scl * (1.f / (1.f + expf(-(acc + i3b))));
            s->intv[rr][tt] = val;
            size_t base = (size_t)(b0 + rr) * T_LEN + tt;
            out[(size_t)BT + base]   = Xb[6];                          // HVAC_list
            out[3*(size_t)BT + base] = (tt >= WINDOW) ? val : 0.f;     // Int_list
            if (tt < WINDOW) {
                out[base]                = Xb[0];                      // TOut[:, :w]
                out[2*(size_t)BT + base] = 0.f;                        // Ext zeros
                s->tout[rr][tt] = Xb[0];
            }
        }
        for (int idx = tid; idx < R_ROWS * (HID/2); idx += NTHR)
            s->h2[idx >> 6][idx & 63] = pack2(1.f, 1.f);
        if (tid < R_ROWS)
            s->Esm[tid] = X[(size_t)(b0 + tid) * (T_LEN * 7) + WINDOW * 7];
    }
    float cst = 1.f;   // cell state for (r2, u2)
    __syncthreads();

    // ================= main sequential time loop =================
    for (int i = WINDOW; i < T_LEN; ++i) {
        const bool  enc   = (i < ENCO);
        const float ratio = enc ? (float)i * (1.f / ENCO) : 0.f;

        // ---- window build (32 threads) ----
        if (tid < R_ROWS * WINDOW) {
            int rr = tid >> 3, tt = tid & 7;
            int pos = i - (WINDOW - 1) + tt;
            const float* Xb = X + (size_t)(b0 + rr) * (T_LEN * 7);
            float TO;
            if (tt == WINDOW - 1) {
                TO = s->Esm[rr];
                s->tout[rr][i] = TO;
                out[(size_t)(b0 + rr) * T_LEN + i] = TO;
            } else {
                TO = s->tout[rr][pos];
            }
            float e0 = enc ? fmaf(Xb[pos * 7], ratio, TO * (1.f - ratio)) : TO;
            s->xv[rr][tt][0] = e0;
            #pragma unroll
            for (int j = 1; j < 5; ++j) s->xv[rr][tt][j] = Xb[pos * 7 + j];
        }
        __syncthreads();

        // ---- 8 LSTM sub-steps, 2 barriers each ----
        #pragma unroll 1
        for (int st = 0; st < WINDOW; ++st) {
            // partial dots for cols c2, c2+256, rows 0..3, over my K-half
            ull a[8] = {0, 0, 0, 0, 0, 0, 0, 0};
            if (kh == 0) dot_half<0>(s, c2, tA, tB, a);
            else         dot_half<12>(s, c2, tA, tB, a);

            float init0[R_ROWS], init1[R_ROWS];
            if (kh == 0) {
                #pragma unroll
                for (int r = 0; r < R_ROWS; ++r) {
                    float v0 = btA, v1 = btB;
                    #pragma unroll
                    for (int j = 0; j < 5; ++j) {
                        float xj = s->xv[r][st][j];
                        v0 = fmaf(xj, wihA[j], v0);
                        v1 = fmaf(xj, wihB[j], v1);
                    }
                    init0[r] = v0; init1[r] = v1;
                }
            } else {
                #pragma unroll
                for (int r = 0; r < R_ROWS; ++r) { init0[r] = 0.f; init1[r] = 0.f; }
            }

            s->gp[kh][0][c2]       = init0[0] + lo32(a[0]) + hi32(a[0]);
            s->gp[kh][1][c2]       = init0[1] + lo32(a[1]) + hi32(a[1]);
            s->gp[kh][2][c2]       = init0[2] + lo32(a[2]) + hi32(a[2]);
            s->gp[kh][3][c2]       = init0[3] + lo32(a[3]) + hi32(a[3]);
            s->gp[kh][0][c2 + 256] = init1[0] + lo32(a[4]) + hi32(a[4]);
            s->gp[kh][1][c2 + 256] = init1[1] + lo32(a[5]) + hi32(a[5]);
            s->gp[kh][2][c2 + 256] = init1[2] + lo32(a[6]) + hi32(a[6]);
            s->gp[kh][3][c2 + 256] = init1[3] + lo32(a[7]) + hi32(a[7]);
            __syncthreads();

            // phase 2: thread-local c/h for (r2, u2)
            {
                float gi = s->gp[0][r2][u2]       + s->gp[1][r2][u2];
                float gf = s->gp[0][r2][u2 + 128] + s->gp[1][r2][u2 + 128];
                float gg = s->gp[0][r2][u2 + 256] + s->gp[1][r2][u2 + 256];
                float go = s->gp[0][r2][u2 + 384] + s->gp[1][r2][u2 + 384];
                cst = sigf(gf) * cst + sigf(gi) * tanhf_(gg);
                float hv = sigf(go) * tanhf_(cst);
                reinterpret_cast<float*>(&s->h2[0][0])[r2 * HID + u2] = hv;
            }
            __syncthreads();
        }

        // ---- ext head (first 256 threads, 2 rows each) ----
        if (kh == 0) {
            const int rA = r2;            // 0 or 1 (since tid < 256)
            const ull* hA = s->h2[rA];
            const ull* hB = s->h2[rA + 2];
            ull A0 = 0, A1 = 0;
            #pragma unroll 8
            for (int k2 = 0; k2 < 64; ++k2) {
                ull w = __ldg(&g_fc1p[k2 * HID + u2]);
                A0 = ffma2(w, hA[k2], A0);
                A1 = ffma2(w, hB[k2], A1);
            }
            float p0 = fmaxf(lo32(A0) + hi32(A0) + b1r, 0.f) * w2r;
            float p1 = fmaxf(lo32(A1) + hi32(A1) + b1r, 0.f) * w2r;
            #pragma unroll
            for (int m = 16; m > 0; m >>= 1) {
                p0 += __shfl_xor_sync(0xFFFFFFFFu, p0, m);
                p1 += __shfl_xor_sync(0xFFFFFFFFu, p1, m);
            }
            if ((tid & 31) == 0) {
                int w8 = tid >> 5;                 // 0..7
                s->red[rA][w8 & 3]     = p0;
                s->red[rA + 2][w8 & 3] = p1;
            }
        }
        __syncthreads();

        // ---- scalar tail ----
        if (tid < R_ROWS) {
            int rr = tid;
            float dot = s->red[rr][0] + s->red[rr][1] + s->red[rr][2] + s->red[rr][3];
            float ext = dot + fcb2;
            const float* Xb = X + (size_t)(b0 + rr) * (T_LEN * 7);
            float hv = Xb[i * 7 + 6];
            float it = s->intv[rr][i];
            float total = ext + hv + it;
            out[2*(size_t)BT + (size_t)(b0 + rr) * T_LEN + i] = ext;
            float E = s->Esm[rr];
            if (enc) E = ratio * Xb[i * 7] + (1.f - ratio) * E + total * zone;
            else     E = total * zone + E;
            s->Esm[rr] = E;
        }
        __syncthreads();
    }
}

extern "C" void kernel_launch(void* const* d_in, const int* in_sizes, int n_in,
                              void* d_out, int out_size) {
    const float* X       = (const float*)d_in[0];
    const float* W_ih    = (const float*)d_in[1];
    const float* W_hh    = (const float*)d_in[2];
    const float* b_ih    = (const float*)d_in[3];
    const float* b_hh    = (const float*)d_in[4];
    const float* fc1_w   = (const float*)d_in[5];
    const float* fc1_b   = (const float*)d_in[6];
    const float* fc2_w   = (const float*)d_in[7];
    const float* fc2_b   = (const float*)d_in[8];
    const float* int1_w  = (const float*)d_in[9];
    const float* int1_b  = (const float*)d_in[10];
    const float* int3_w  = (const float*)d_in[11];
    const float* int3_b  = (const float*)d_in[12];
    const float* scale_w = (const float*)d_in[13];
    const float* zone_w  = (const float*)d_in[14];
    float* out = (float*)d_out;

    prep_weights<<<64, 128>>>(fc1_w, W_hh);

    size_t smem = sizeof(Smem);
    cudaFuncSetAttribute(modnn_kernel, cudaFuncAttributeMaxDynamicSharedMemorySize, (int)smem);
    modnn_kernel<<<NCTA, NTHR, smem>>>(X, W_ih, W_hh, b_ih, b_hh,
                                       fc1_b, fc2_w, fc2_b,
                                       int1_w, int1_b, int3_w, int3_b,
                                       scale_w, zone_w, out);
}

// round 15
// speedup vs baseline: 2.2759x; 2.1892x over previous
#include <cuda_runtime.h>
#include <cstdint>
#include <cstddef>
#include <math.h>

#define B_TOTAL 512
#define T_LEN   256
#define HID     128
#define G4      512
#define WINDOW  8
#define ENCO    128
#define R_ROWS  4
#define NCTA    128
#define NTHR    256
#define K4_SM   20           // k-quads in smem: k 0..79
#define TAIL_P  24           // k-pairs 40..63 (k 80..127) in registers, per column
#define BT      (B_TOTAL * T_LEN)

typedef unsigned long long ull;

__device__ __forceinline__ ull ffma2(ull a, ull b, ull c) {
    ull d;
    asm("fma.rn.f32x2 %0, %1, %2, %3;" : "=l"(d) : "l"(a), "l"(b), "l"(c));
    return d;
}
__device__ __forceinline__ float lo32(ull v) { return __uint_as_float((unsigned)v); }
__device__ __forceinline__ float hi32(ull v) { return __uint_as_float((unsigned)(v >> 32)); }
__device__ __forceinline__ ull pack2(float a, float b) {
    return (ull)__float_as_uint(a) | ((ull)__float_as_uint(b) << 32);
}
__device__ __forceinline__ float sigf(float x) {
    return __fdividef(1.f, 1.f + __expf(-x));
}
__device__ __forceinline__ float tanhf_(float x) {
    return 1.f - __fdividef(2.f, 1.f + __expf(2.f * x));
}

struct Smem {
    ull   Wq[K4_SM][G4][2];       // 163840 B : W_hh k0..79, 16B per (k4,col)
    alignas(16) ull h2[R_ROWS][HID/2];  // 2048 B : hidden state packed pairs
    float g[R_ROWS][G4];          //   8192 B : gate pre-activations (init staging too)
    float tout[R_ROWS][T_LEN];    //   4096 B
    float intv[R_ROWS][T_LEN];    //   4096 B
    float xv[R_ROWS][WINDOW][5];  //    640 B
    float fc1b[HID];              //    512 B
    float fc2w[HID];              //    512 B
    float Esm[R_ROWS];            //     16 B
    float red[R_ROWS][4];         //     64 B
};

// fc1 weights as transposed pairs
__device__ ull g_fc1p[64 * HID];

__global__ void prep_fc1(const float* __restrict__ fc1_w) {
    int idx = blockIdx.x * blockDim.x + threadIdx.x;
    if (idx < 64 * HID) {
        int k2 = idx >> 7, u = idx & 127;
        g_fc1p[idx] = pack2(fc1_w[u * HID + 2 * k2], fc1_w[u * HID + 2 * k2 + 1]);
    }
}

__global__ __launch_bounds__(NTHR, 1)
void modnn_kernel(const float* __restrict__ X,
                  const float* __restrict__ W_ih, const float* __restrict__ W_hh,
                  const float* __restrict__ b_ih, const float* __restrict__ b_hh,
                  const float* __restrict__ fc1_b,
                  const float* __restrict__ fc2_w, const float* __restrict__ fc2_b,
                  const float* __restrict__ int1_w, const float* __restrict__ int1_b,
                  const float* __restrict__ int3_w, const float* __restrict__ int3_b,
                  const float* __restrict__ scale_w, const float* __restrict__ zone_w,
                  float* __restrict__ out)
{
    extern __shared__ char smem_raw[];
    Smem* s = reinterpret_cast<Smem*>(smem_raw);
    const int tid = threadIdx.x;
    const int b0  = blockIdx.x * R_ROWS;

    // ---- stage W_hh k=0..79 as [k4][col] 16B quads ----
    for (int idx = tid; idx < K4_SM * G4; idx += NTHR) {
        int k4 = idx >> 9, col = idx & 511;
        const float* wr = W_hh + (size_t)col * HID + 4 * k4;
        s->Wq[k4][col][0] = pack2(wr[0], wr[1]);
        s->Wq[k4][col][1] = pack2(wr[2], wr[3]);
    }
    if (tid < HID) { s->fc1b[tid] = fc1_b[tid]; s->fc2w[tid] = fc2_w[tid]; }

    // stage int-module weights into g area (reused later)
    {
        float* tmp = &s->g[0][0];
        for (int idx = tid; idx < HID * 3; idx += NTHR) tmp[idx] = int1_w[idx];
        for (int idx = tid; idx < HID; idx += NTHR) {
            tmp[384 + idx] = int1_b[idx];
            tmp[512 + idx] = int3_w[idx];
        }
    }

    // ---- per-thread invariants in registers ----
    float wihA[5], wihB[5];
    #pragma unroll
    for (int j = 0; j < 5; ++j) {
        wihA[j] = W_ih[tid * 5 + j];
        wihB[j] = W_ih[(tid + 256) * 5 + j];
    }
    const float btA = b_ih[tid] + b_hh[tid];
    const float btB = b_ih[tid + 256] + b_hh[tid + 256];

    // ---- W_hh tail (k 80..127 = pairs 40..63) in registers, 2 columns ----
    ull wt0[TAIL_P], wt1[TAIL_P];
    {
        const ull* p0 = reinterpret_cast<const ull*>(W_hh + (size_t)tid * HID + 80);
        const ull* p1 = reinterpret_cast<const ull*>(W_hh + (size_t)(tid + 256) * HID + 80);
        #pragma unroll
        for (int j = 0; j < TAIL_P; ++j) { wt0[j] = p0[j]; wt1[j] = p1[j]; }
    }

    const float zone = zone_w[0];
    const float fcb2 = fc2_b[0];
    const float i3b  = int3_b[0];
    const float scl  = scale_w[0];
    __syncthreads();

    // ---- precompute int_all; emit constant outputs; init tout/h/Esm ----
    {
        const float* tmp = &s->g[0][0];
        for (int it = tid; it < R_ROWS * T_LEN; it += NTHR) {
            int r = it >> 8, tt = it & 255;
            const float* Xb = X + (size_t)(b0 + r) * (T_LEN * 7) + tt * 7;
            float x0 = Xb[3], x1 = Xb[4], x2 = Xb[5];
            float acc = 0.f;
            #pragma unroll 8
            for (int u = 0; u < HID; ++u) {
                float v = fmaf(tmp[u*3], x0, fmaf(tmp[u*3+1], x1, fmaf(tmp[u*3+2], x2, tmp[384+u])));
                v = fmaxf(v, 0.f);
                acc = fmaf(v, tmp[512 + u], acc);
            }
            float val = scl * (1.f / (1.f + expf(-(acc + i3b))));
            s->intv[r][tt] = val;
            size_t base = (size_t)(b0 + r) * T_LEN + tt;
            out[(size_t)BT + base]   = Xb[6];                          // HVAC_list
            out[3*(size_t)BT + base] = (tt >= WINDOW) ? val : 0.f;     // Int_list
            if (tt < WINDOW) {
                out[base]                = Xb[0];                      // TOut[:, :w]
                out[2*(size_t)BT + base] = 0.f;                        // Ext zeros
                s->tout[r][tt] = Xb[0];
            }
        }
        for (int idx = tid; idx < R_ROWS * (HID/2); idx += NTHR)
            s->h2[idx >> 6][idx & 63] = pack2(1.f, 1.f);
        if (tid < R_ROWS)
            s->Esm[tid] = X[(size_t)(b0 + tid) * (T_LEN * 7) + WINDOW * 7];
    }
    float c0 = 1.f, c1 = 1.f;
    const int rA = tid >> 7;       // phase-2 / fc1 rows: rA and rA+2
    const int uu = tid & 127;
    __syncthreads();

    // ================= main sequential time loop =================
    for (int i = WINDOW; i < T_LEN; ++i) {
        const bool  enc   = (i < ENCO);
        const float ratio = enc ? (float)i * (1.f / ENCO) : 0.f;

        // ---- window build ----
        if (tid < R_ROWS * WINDOW) {
            int r = tid >> 3, tt = tid & 7;
            int pos = i - (WINDOW - 1) + tt;
            const float* Xb = X + (size_t)(b0 + r) * (T_LEN * 7);
            float TO;
            if (tt == WINDOW - 1) {
                TO = s->Esm[r];
                s->tout[r][i] = TO;
                out[(size_t)(b0 + r) * T_LEN + i] = TO;
            } else {
                TO = s->tout[r][pos];
            }
            float e0 = enc ? fmaf(Xb[pos * 7], ratio, TO * (1.f - ratio)) : TO;
            s->xv[r][tt][0] = e0;
            #pragma unroll
            for (int j = 1; j < 5; ++j) s->xv[r][tt][j] = Xb[pos * 7 + j];
        }
        __syncthreads();

        // ---- 8 LSTM sub-steps ----
        #pragma unroll 1
        for (int st = 0; st < WINDOW; ++st) {
            ull a00 = 0, a01 = 0, a02 = 0, a03 = 0;
            ull a10 = 0, a11 = 0, a12 = 0, a13 = 0;
            const ulonglong2* hq0 = reinterpret_cast<const ulonglong2*>(s->h2[0]);
            const ulonglong2* hq1 = reinterpret_cast<const ulonglong2*>(s->h2[1]);
            const ulonglong2* hq2 = reinterpret_cast<const ulonglong2*>(s->h2[2]);
            const ulonglong2* hq3 = reinterpret_cast<const ulonglong2*>(s->h2[3]);
            // smem part: k-quads 0..19 (k 0..79)
            #pragma unroll 5
            for (int k4 = 0; k4 < K4_SM; ++k4) {
                ulonglong2 w0 = *reinterpret_cast<const ulonglong2*>(&s->Wq[k4][tid][0]);
                ulonglong2 w1 = *reinterpret_cast<const ulonglong2*>(&s->Wq[k4][tid + 256][0]);
                ulonglong2 h0 = hq0[k4], h1 = hq1[k4], h2 = hq2[k4], h3 = hq3[k4];
                a00 = ffma2(w0.x, h0.x, a00);  a00 = ffma2(w0.y, h0.y, a00);
                a10 = ffma2(w1.x, h0.x, a10);  a10 = ffma2(w1.y, h0.y, a10);
                a01 = ffma2(w0.x, h1.x, a01);  a01 = ffma2(w0.y, h1.y, a01);
                a11 = ffma2(w1.x, h1.x, a11);  a11 = ffma2(w1.y, h1.y, a11);
                a02 = ffma2(w0.x, h2.x, a02);  a02 = ffma2(w0.y, h2.y, a02);
                a12 = ffma2(w1.x, h2.x, a12);  a12 = ffma2(w1.y, h2.y, a12);
                a03 = ffma2(w0.x, h3.x, a03);  a03 = ffma2(w0.y, h3.y, a03);
                a13 = ffma2(w1.x, h3.x, a13);  a13 = ffma2(w1.y, h3.y, a13);
            }
            // register tail: FULLY UNROLLED so wt0/wt1 stay in registers
            #pragma unroll
            for (int q = 0; q < TAIL_P / 2; ++q) {
                ulonglong2 h0 = hq0[K4_SM + q], h1 = hq1[K4_SM + q];
                ulonglong2 h2 = hq2[K4_SM + q], h3 = hq3[K4_SM + q];
                ull wa0 = wt0[2*q], wb0 = wt0[2*q+1];
                ull wa1 = wt1[2*q], wb1 = wt1[2*q+1];
                a00 = ffma2(wa0, h0.x, a00);  a00 = ffma2(wb0, h0.y, a00);
                a10 = ffma2(wa1, h0.x, a10);  a10 = ffma2(wb1, h0.y, a10);
                a01 = ffma2(wa0, h1.x, a01);  a01 = ffma2(wb0, h1.y, a01);
                a11 = ffma2(wa1, h1.x, a11);  a11 = ffma2(wb1, h1.y, a11);
                a02 = ffma2(wa0, h2.x, a02);  a02 = ffma2(wb0, h2.y, a02);
                a12 = ffma2(wa1, h2.x, a12);  a12 = ffma2(wb1, h2.y, a12);
                a03 = ffma2(wa0, h3.x, a03);  a03 = ffma2(wb0, h3.y, a03);
                a13 = ffma2(wa1, h3.x, a13);  a13 = ffma2(wb1, h3.y, a13);
            }
            // x-part computed AFTER the dot (short live ranges)
            float init0[R_ROWS], init1[R_ROWS];
            #pragma unroll
            for (int r = 0; r < R_ROWS; ++r) {
                float v0 = btA, v1 = btB;
                #pragma unroll
                for (int j = 0; j < 5; ++j) {
                    float xj = s->xv[r][st][j];
                    v0 = fmaf(xj, wihA[j], v0);
                    v1 = fmaf(xj, wihB[j], v1);
                }
                init0[r] = v0; init1[r] = v1;
            }
            s->g[0][tid]       = init0[0] + lo32(a00) + hi32(a00);
            s->g[1][tid]       = init0[1] + lo32(a01) + hi32(a01);
            s->g[2][tid]       = init0[2] + lo32(a02) + hi32(a02);
            s->g[3][tid]       = init0[3] + lo32(a03) + hi32(a03);
            s->g[0][tid + 256] = init1[0] + lo32(a10) + hi32(a10);
            s->g[1][tid + 256] = init1[1] + lo32(a11) + hi32(a11);
            s->g[2][tid + 256] = init1[2] + lo32(a12) + hi32(a12);
            s->g[3][tid + 256] = init1[3] + lo32(a13) + hi32(a13);
            __syncthreads();

            // phase 2: c/h update for (rA, uu) and (rA+2, uu) — fast activations
            {
                float* hf = reinterpret_cast<float*>(&s->h2[0][0]);
                {
                    int r = rA;
                    float gi = s->g[r][uu], gf = s->g[r][uu + 128];
                    float gg = s->g[r][uu + 256], go = s->g[r][uu + 384];
                    c0 = sigf(gf) * c0 + sigf(gi) * tanhf_(gg);
                    hf[r * HID + uu] = sigf(go) * tanhf_(c0);
                }
                {
                    int r = rA + 2;
                    float gi = s->g[r][uu], gf = s->g[r][uu + 128];
                    float gg = s->g[r][uu + 256], go = s->g[r][uu + 384];
                    c1 = sigf(gf) * c1 + sigf(gi) * tanhf_(gg);
                    hf[r * HID + uu] = sigf(go) * tanhf_(c1);
                }
            }
            __syncthreads();
        }

        // ---- ext head ----
        {
            const ull* hA = s->h2[rA];
            const ull* hB = s->h2[rA + 2];
            ull A0 = 0, A1 = 0;
            #pragma unroll 8
            for (int k2 = 0; k2 < 64; ++k2) {
                ull w = __ldg(&g_fc1p[k2 * HID + uu]);
                A0 = ffma2(w, hA[k2], A0);
                A1 = ffma2(w, hB[k2], A1);
            }
            float b1 = s->fc1b[uu], w2 = s->fc2w[uu];
            float p0 = fmaxf(lo32(A0) + hi32(A0) + b1, 0.f) * w2;
            float p1 = fmaxf(lo32(A1) + hi32(A1) + b1, 0.f) * w2;
            #pragma unroll
            for (int m = 16; m > 0; m >>= 1) {
                p0 += __shfl_xor_sync(0xFFFFFFFFu, p0, m);
                p1 += __shfl_xor_sync(0xFFFFFFFFu, p1, m);
            }
            if ((tid & 31) == 0) {
                int w8 = tid >> 5;
                s->red[rA][w8 & 3]     = p0;
                s->red[rA + 2][w8 & 3] = p1;
            }
        }
        __syncthreads();

        // ---- scalar tail ----
        if (tid < R_ROWS) {
            int r = tid;
            float dot = s->red[r][0] + s->red[r][1] + s->red[r][2] + s->red[r][3];
            float ext = dot + fcb2;
            const float* Xb = X + (size_t)(b0 + r) * (T_LEN * 7);
            float hv = Xb[i * 7 + 6];
            float it = s->intv[r][i];
            float total = ext + hv + it;
            out[2*(size_t)BT + (size_t)(b0 + r) * T_LEN + i] = ext;
            float E = s->Esm[r];
            if (enc) E = ratio * Xb[i * 7] + (1.f - ratio) * E + total * zone;
            else     E = total * zone + E;
            s->Esm[r] = E;
        }
        __syncthreads();
    }
}

extern "C" void kernel_launch(void* const* d_in, const int* in_sizes, int n_in,
                              void* d_out, int out_size) {
    const float* X       = (const float*)d_in[0];
    const float* W_ih    = (const float*)d_in[1];
    const float* W_hh    = (const float*)d_in[2];
    const float* b_ih    = (const float*)d_in[3];
    const float* b_hh    = (const float*)d_in[4];
    const float* fc1_w   = (const float*)d_in[5];
    const float* fc1_b   = (const float*)d_in[6];
    const float* fc2_w   = (const float*)d_in[7];
    const float* fc2_b   = (const float*)d_in[8];
    const float* int1_w  = (const float*)d_in[9];
    const float* int1_b  = (const float*)d_in[10];
    const float* int3_w  = (const float*)d_in[11];
    const float* int3_b  = (const float*)d_in[12];
    const float* scale_w = (const float*)d_in[13];
    const float* zone_w  = (const float*)d_in[14];
    float* out = (float*)d_out;

    prep_fc1<<<64, 128>>>(fc1_w);

    size_t smem = sizeof(Smem);
    cudaFuncSetAttribute(modnn_kernel, cudaFuncAttributeMaxDynamicSharedMemorySize, (int)smem);
    modnn_kernel<<<NCTA, NTHR, smem>>>(X, W_ih, W_hh, b_ih, b_hh,
                                       fc1_b, fc2_w, fc2_b,
                                       int1_w, int1_b, int3_w, int3_b,
                                       scale_w, zone_w, out);
}